// round 2
// baseline (speedup 1.0000x reference)
#include <cuda_runtime.h>
#include <math.h>
#include <stdint.h>

// ---------------- problem dims ----------------
#define MTOT   16384      // B*L = 16*1024
#define DMODEL 512
#define DLOW   256
#define DMH    258
#define DINNER 516
#define DSTATE 16
#define DTRANK 17
#define XDBL_C 49         // DTRANK + 2*DSTATE
#define FCOLS  514        // 2*257 packed freq channels
#define LSEQ   1024
#define NB     16

// ---------------- scratch (device globals; no allocation allowed) ----------------
__device__ float g_FT[FCOLS * DMODEL];          // forward DFT weights (N=514, K=512) NT
__device__ float g_G [DMODEL * FCOLS];          // inverse DFT weights (N=512, K=514) NT
__device__ float g_Wt[DLOW * 512];              // taylor weights (N=256, K=512) NT
__device__ float g_bias_t[DLOW];                // taylor total bias
__device__ float g_xfcat[(size_t)MTOT * FCOLS]; // rfft packed channels
__device__ float g_feat [(size_t)MTOT * 512];   // [x_l, x_l^2]
__device__ float g_xz   [(size_t)MTOT * 1032];  // in_proj out
__device__ float g_xm   [(size_t)MTOT * DINNER];// conv+silu out
__device__ float g_xdbl [(size_t)MTOT * XDBL_C];// x_proj out
__device__ float g_dt   [(size_t)MTOT * DINNER];// softplus(dt)
__device__ float g_ys   [(size_t)MTOT * DINNER];// scan out (gated)
__device__ float g_ycat [(size_t)MTOT * FCOLS]; // [y_l | y_h]
__device__ float g_ymid [(size_t)MTOT * DMODEL];// irfft out (pre-norm)

// ---------------- weight-prep kernels ----------------
// rfft ortho scale = 1/sqrt(512)
#define ORTHO_SCALE 0.04419417382415922f

__global__ void k_gen_FT() {
    int idx = blockIdx.x * blockDim.x + threadIdx.x;
    if (idx >= FCOLS * DMODEL) return;
    int col = idx / DMODEL;     // output channel 0..513
    int n   = idx - col * DMODEL;
    int k, isIm;
    if (col < 128)      { k = col;             isIm = 0; }
    else if (col < 256) { k = col - 128;       isIm = 1; }
    else if (col < 385) { k = col - 256 + 128; isIm = 0; }  // Re k=128..256
    else                { k = col - 385 + 128; isIm = 1; }  // Im k=128..256
    // angle = 2*pi*k*n/512 -> pi * (k*n/256); k*n < 2^24 so exact in float
    float a = (float)(k * n) * (1.0f / 256.0f);
    float s, c;
    sincospif(a, &s, &c);
    g_FT[(size_t)col * DMODEL + n] = isIm ? (-s * ORTHO_SCALE) : (c * ORTHO_SCALE);
}

__global__ void k_gen_G() {
    int idx = blockIdx.x * blockDim.x + threadIdx.x;
    if (idx >= DMODEL * FCOLS) return;
    int n = idx / FCOLS;
    int j = idx - n * FCOLS;
    int k = j >> 1;
    float a = (float)(k * n) * (1.0f / 256.0f);
    float s, c;
    sincospif(a, &s, &c);
    float val;
    if ((j & 1) == 0) {          // real component coefficient
        float w = (k == 0 || k == 256) ? 1.0f : 2.0f;
        val = w * c * ORTHO_SCALE;
    } else {                     // imag component (DC/Nyquist imag ignored by irfft)
        val = (k == 0 || k == 256) ? 0.0f : (-2.0f * s * ORTHO_SCALE);
    }
    g_G[(size_t)n * FCOLS + j] = val;
}

__global__ void k_build_Wt(const float* __restrict__ coeffs) {
    int idx = blockIdx.x * blockDim.x + threadIdx.x;   // over 256*256
    if (idx >= DLOW * DLOW) return;
    int u = idx / DLOW;
    int i = idx - u * DLOW;
    const float* cp = coeffs + ((size_t)u * DLOW + i) * 3;
    g_Wt[(size_t)u * 512 + i]        = cp[1];
    g_Wt[(size_t)u * 512 + 256 + i]  = cp[2];
}

__global__ void k_build_bias(const float* __restrict__ coeffs,
                             const float* __restrict__ tb) {
    int u = threadIdx.x;           // one block, 256 threads
    float acc = tb[u];
    const float* cp = coeffs + (size_t)u * DLOW * 3;
    for (int i = 0; i < DLOW; i++) acc += cp[i * 3];
    g_bias_t[u] = acc;
}

// ---------------- generic NT SGEMM: C[m,n] = sum_k A[m,k]*B[n,k] ----------------
// BM=BN=128, BK=8, 256 threads, 8x8 per thread (split 4+4 halves), reg prefetch.
// M must be a multiple of 128 (true here: 16384). N,K arbitrary (guarded).
__global__ void __launch_bounds__(256)
sgemm_nt(const float* __restrict__ A, int lda,
         const float* __restrict__ B, int ldb,
         float* __restrict__ C, int ldc,
         int N, int K,
         const float* __restrict__ bias, int act)
{
    __shared__ float As[8][128];
    __shared__ float Bs[8][128];

    const int tid = threadIdx.x;
    const int m0 = blockIdx.y * 128;
    const int n0 = blockIdx.x * 128;

    const int a_row = tid >> 1;          // 0..127
    const int ld_k  = (tid & 1) * 4;     // 0 or 4
    const bool b_valid = (n0 + a_row) < N;

    const float* Aptr = A + (size_t)(m0 + a_row) * lda;
    const float* Bptr = B + (size_t)(n0 + a_row) * ldb;

    const int tx = tid & 15;
    const int ty = tid >> 4;

    float acc[8][8];
#pragma unroll
    for (int i = 0; i < 8; i++)
#pragma unroll
        for (int j = 0; j < 8; j++) acc[i][j] = 0.0f;

    float a_reg[4], b_reg[4];
    // prologue: load k-tile 0 into regs
#pragma unroll
    for (int i = 0; i < 4; i++) {
        int kk = ld_k + i;
        a_reg[i] = (kk < K) ? Aptr[kk] : 0.0f;
        b_reg[i] = (b_valid && kk < K) ? Bptr[kk] : 0.0f;
    }

    for (int k0 = 0; k0 < K; k0 += 8) {
        // commit prefetched regs to smem
#pragma unroll
        for (int i = 0; i < 4; i++) {
            As[ld_k + i][a_row] = a_reg[i];
            Bs[ld_k + i][a_row] = b_reg[i];
        }
        __syncthreads();

        // prefetch next tile
        int kn = k0 + 8;
        if (kn < K) {
#pragma unroll
            for (int i = 0; i < 4; i++) {
                int kk = kn + ld_k + i;
                a_reg[i] = (kk < K) ? Aptr[kk] : 0.0f;
                b_reg[i] = (b_valid && kk < K) ? Bptr[kk] : 0.0f;
            }
        }

        // compute
#pragma unroll
        for (int kk = 0; kk < 8; kk++) {
            float4 a0 = *reinterpret_cast<const float4*>(&As[kk][ty * 4]);
            float4 a1 = *reinterpret_cast<const float4*>(&As[kk][64 + ty * 4]);
            float4 b0 = *reinterpret_cast<const float4*>(&Bs[kk][tx * 4]);
            float4 b1 = *reinterpret_cast<const float4*>(&Bs[kk][64 + tx * 4]);
            float av[8] = {a0.x, a0.y, a0.z, a0.w, a1.x, a1.y, a1.z, a1.w};
            float bv[8] = {b0.x, b0.y, b0.z, b0.w, b1.x, b1.y, b1.z, b1.w};
#pragma unroll
            for (int i = 0; i < 8; i++)
#pragma unroll
                for (int j = 0; j < 8; j++)
                    acc[i][j] = fmaf(av[i], bv[j], acc[i][j]);
        }
        __syncthreads();
    }

    // epilogue
#pragma unroll
    for (int i = 0; i < 8; i++) {
        int m_l = (i < 4) ? (ty * 4 + i) : (64 + ty * 4 + (i - 4));
        size_t crow = (size_t)(m0 + m_l) * ldc;
#pragma unroll
        for (int j = 0; j < 8; j++) {
            int n_l = (j < 4) ? (tx * 4 + j) : (64 + tx * 4 + (j - 4));
            int n = n0 + n_l;
            if (n < N) {
                float v = acc[i][j];
                if (bias) v += bias[n];
                if (act == 1) {  // softplus (stable)
                    v = fmaxf(v, 0.0f) + log1pf(__expf(-fabsf(v)));
                }
                C[crow + n] = v;
            }
        }
    }
}

// ---------------- taylor feature build: [x, x^2] ----------------
__global__ void k_feat() {
    int idx = blockIdx.x * blockDim.x + threadIdx.x;   // MTOT*256
    if (idx >= MTOT * DLOW) return;
    int m = idx / DLOW;
    int i = idx - m * DLOW;
    float v = g_xfcat[(size_t)m * FCOLS + i];
    g_feat[(size_t)m * 512 + i]       = v;
    g_feat[(size_t)m * 512 + 256 + i] = v * v;
}

// ---------------- depthwise causal conv(4) + silu ----------------
__global__ void k_conv_silu(const float* __restrict__ conv_w,
                            const float* __restrict__ conv_b) {
    int idx = blockIdx.x * blockDim.x + threadIdx.x;   // MTOT*DINNER
    if (idx >= MTOT * DINNER) return;
    int m = idx / DINNER;
    int d = idx - m * DINNER;
    int l = m & (LSEQ - 1);
    const float* w = conv_w + d * 4;
    float acc = conv_b[d];
#pragma unroll
    for (int j = 0; j < 4; j++) {
        int ls = l - 3 + j;
        if (ls >= 0) acc += g_xz[(size_t)(m - 3 + j) * 1032 + d] * w[j];
    }
    // silu
    float sg = 1.0f / (1.0f + __expf(-acc));
    g_xm[(size_t)m * DINNER + d] = acc * sg;
}

// ---------------- selective scan (thread per (b,d,s), 16-lane reduce) ----------
__global__ void k_scan(const float* __restrict__ A_log,
                       const float* __restrict__ D_param) {
    int g = blockIdx.x * 8 + (threadIdx.x >> 4);   // group index over (b,d)
    int s = threadIdx.x & 15;
    if (g >= NB * DINNER) return;
    int b = g / DINNER;
    int d = g - b * DINNER;

    const float A  = -__expf(A_log[d * DSTATE + s]);
    const float Dv = D_param[d];

    const size_t rowb = (size_t)b * LSEQ;
    const float* dtp = g_dt   + rowb * DINNER + d;
    const float* xp  = g_xm   + rowb * DINNER + d;
    const float* Bp  = g_xdbl + rowb * XDBL_C + DTRANK + s;
    const float* Cp  = g_xdbl + rowb * XDBL_C + DTRANK + DSTATE + s;
    const float* zp  = g_xz   + rowb * 1032 + DINNER + d;
    float*       yp  = g_ys   + rowb * DINNER + d;

    float h = 0.0f;
    for (int t = 0; t < LSEQ; t++) {
        float dtv = dtp[(size_t)t * DINNER];
        float xv  = xp [(size_t)t * DINNER];
        float Bv  = Bp [(size_t)t * XDBL_C];
        float Cv  = Cp [(size_t)t * XDBL_C];
        h = __expf(dtv * A) * h + (dtv * xv) * Bv;
        float p = h * Cv;
        p += __shfl_xor_sync(0xffffffffu, p, 1);
        p += __shfl_xor_sync(0xffffffffu, p, 2);
        p += __shfl_xor_sync(0xffffffffu, p, 4);
        p += __shfl_xor_sync(0xffffffffu, p, 8);
        if (s == 0) {
            float zv = zp[(size_t)t * 1032];
            float sg = 1.0f / (1.0f + __expf(-zv));
            yp[(size_t)t * DINNER] = (p + xv * Dv) * (zv * sg);
        }
    }
}

// ---------------- RMSNorm * w + residual ----------------
__global__ void k_norm(const float* __restrict__ x,
                       const float* __restrict__ nw,
                       float* __restrict__ out) {
    int m = blockIdx.x;
    const float* yr = g_ymid + (size_t)m * DMODEL;
    float v[4];
    float ss = 0.0f;
#pragma unroll
    for (int i = 0; i < 4; i++) {
        v[i] = yr[threadIdx.x + i * 128];
        ss += v[i] * v[i];
    }
    // reduce 128 threads
    __shared__ float red[4];
#pragma unroll
    for (int o = 16; o > 0; o >>= 1) ss += __shfl_xor_sync(0xffffffffu, ss, o);
    if ((threadIdx.x & 31) == 0) red[threadIdx.x >> 5] = ss;
    __syncthreads();
    float tot = red[0] + red[1] + red[2] + red[3];
    float rs = rsqrtf(tot * (1.0f / DMODEL) + 1e-5f);
#pragma unroll
    for (int i = 0; i < 4; i++) {
        int n = threadIdx.x + i * 128;
        out[(size_t)m * DMODEL + n] = v[i] * rs * nw[n] + x[(size_t)m * DMODEL + n];
    }
}

// ---------------- launch ----------------
static inline dim3 gemm_grid(int N) { return dim3((N + 127) / 128, MTOT / 128); }

extern "C" void kernel_launch(void* const* d_in, const int* in_sizes, int n_in,
                              void* d_out, int out_size) {
    const float* x             = (const float*)d_in[0];
    const float* taylor_coeffs = (const float*)d_in[1];
    const float* taylor_bias   = (const float*)d_in[2];
    const float* in_proj_w     = (const float*)d_in[3];
    const float* conv_w        = (const float*)d_in[4];
    const float* conv_b        = (const float*)d_in[5];
    const float* x_proj_w      = (const float*)d_in[6];
    const float* dt_proj_w     = (const float*)d_in[7];
    const float* dt_proj_b     = (const float*)d_in[8];
    const float* A_log         = (const float*)d_in[9];
    const float* D_param       = (const float*)d_in[10];
    const float* out_proj_w    = (const float*)d_in[11];
    const float* norm_w        = (const float*)d_in[12];
    float* out = (float*)d_out;

    float *p_FT, *p_G, *p_Wt, *p_bias, *p_xfcat, *p_feat, *p_xz, *p_xm,
          *p_xdbl, *p_dt, *p_ys, *p_ycat, *p_ymid;
    cudaGetSymbolAddress((void**)&p_FT,    g_FT);
    cudaGetSymbolAddress((void**)&p_G,     g_G);
    cudaGetSymbolAddress((void**)&p_Wt,    g_Wt);
    cudaGetSymbolAddress((void**)&p_bias,  g_bias_t);
    cudaGetSymbolAddress((void**)&p_xfcat, g_xfcat);
    cudaGetSymbolAddress((void**)&p_feat,  g_feat);
    cudaGetSymbolAddress((void**)&p_xz,    g_xz);
    cudaGetSymbolAddress((void**)&p_xm,    g_xm);
    cudaGetSymbolAddress((void**)&p_xdbl,  g_xdbl);
    cudaGetSymbolAddress((void**)&p_dt,    g_dt);
    cudaGetSymbolAddress((void**)&p_ys,    g_ys);
    cudaGetSymbolAddress((void**)&p_ycat,  g_ycat);
    cudaGetSymbolAddress((void**)&p_ymid,  g_ymid);

    // 1) prep weights
    k_gen_FT<<<(FCOLS * DMODEL + 255) / 256, 256>>>();
    k_gen_G <<<(DMODEL * FCOLS + 255) / 256, 256>>>();
    k_build_Wt<<<(DLOW * DLOW + 255) / 256, 256>>>(taylor_coeffs);
    k_build_bias<<<1, 256>>>(taylor_coeffs, taylor_bias);

    // 2) forward DFT: xfcat = x @ FT^T   (M,514)
    sgemm_nt<<<gemm_grid(FCOLS), 256>>>(x, DMODEL, p_FT, DMODEL,
                                        p_xfcat, FCOLS, FCOLS, DMODEL, nullptr, 0);
    // 3) taylor features + GEMM -> ycat[:, 0:256]
    k_feat<<<(MTOT * DLOW + 255) / 256, 256>>>();
    sgemm_nt<<<gemm_grid(DLOW), 256>>>(p_feat, 512, p_Wt, 512,
                                       p_ycat, FCOLS, DLOW, 512, p_bias, 0);
    // 4) mamba in_proj: xz = xh_cat @ in_proj_w^T  (M,1032)
    sgemm_nt<<<gemm_grid(1032), 256>>>(p_xfcat + 256, FCOLS, in_proj_w, DMH,
                                       p_xz, 1032, 1032, DMH, nullptr, 0);
    // 5) conv + silu -> xm
    k_conv_silu<<<(MTOT * DINNER + 255) / 256, 256>>>(conv_w, conv_b);
    // 6) x_proj: xdbl = xm @ x_proj_w^T  (M,49)
    sgemm_nt<<<gemm_grid(XDBL_C), 256>>>(p_xm, DINNER, x_proj_w, DINNER,
                                         p_xdbl, XDBL_C, XDBL_C, DINNER, nullptr, 0);
    // 7) dt: softplus(xdbl[:, :17] @ dt_proj_w^T + b)  (M,516)
    sgemm_nt<<<gemm_grid(DINNER), 256>>>(p_xdbl, XDBL_C, dt_proj_w, DTRANK,
                                         p_dt, DINNER, DINNER, DTRANK, dt_proj_b, 1);
    // 8) selective scan (fused +x*D and silu(z) gate) -> ys
    k_scan<<<(NB * DINNER + 7) / 8, 128>>>(A_log, D_param);
    // 9) out_proj -> ycat[:, 256:514]
    sgemm_nt<<<gemm_grid(DMH), 256>>>(p_ys, DINNER, out_proj_w, DINNER,
                                      p_ycat + 256, FCOLS, DMH, DINNER, nullptr, 0);
    // 10) inverse DFT: ymid = ycat @ G^T  (M,512)
    sgemm_nt<<<gemm_grid(DMODEL), 256>>>(p_ycat, FCOLS, p_G, FCOLS,
                                         p_ymid, DMODEL, DMODEL, FCOLS, nullptr, 0);
    // 11) RMSNorm + residual
    k_norm<<<MTOT, 128>>>(x, norm_w, out);
}

// round 4
// speedup vs baseline: 1.1710x; 1.1710x over previous
#include <cuda_runtime.h>
#include <math.h>
#include <stdint.h>

// ---------------- problem dims ----------------
#define MTOT   16384      // B*L = 16*1024
#define DMODEL 512
#define DLOW   256
#define DMH    258
#define DINNER 516
#define DSTATE 16
#define DTRANK 17
#define XDBL_C 49         // DTRANK + 2*DSTATE
#define FCOLS  514        // 2*257 packed freq channels
#define FLD    516        // padded leading dim for FCOLS buffers (16B-aligned rows)
#define XDLD   52         // padded leading dim for xdbl
#define LSEQ   1024
#define NB     16

// ---------------- scratch (device globals; no allocation allowed) ----------------
__device__ float g_FT[FCOLS * DMODEL];           // forward DFT weights (N=514, K=512) NT
__device__ float g_G [DMODEL * FLD];             // inverse DFT weights (N=512, K=514) NT, ld=516
__device__ float g_Wt[DLOW * 512];               // taylor weights (N=256, K=512) NT
__device__ float g_bias_t[DLOW];                 // taylor total bias
__device__ float g_xfcat[(size_t)MTOT * FLD + 64];  // rfft packed channels, ld=516
__device__ float g_feat [(size_t)MTOT * 512 + 64];  // [x_l, x_l^2]
__device__ float g_xz   [(size_t)MTOT * 1032 + 64]; // in_proj out
__device__ float g_xm   [(size_t)MTOT * DINNER + 64]; // conv+silu out
__device__ float g_xdbl [(size_t)MTOT * XDLD + 64];   // x_proj out, ld=52
__device__ float g_dt   [(size_t)MTOT * DINNER + 64]; // softplus(dt)
__device__ float g_ys   [(size_t)MTOT * DINNER + 64]; // scan out (gated)
__device__ float g_ycat [(size_t)MTOT * FLD + 64];    // [y_l | y_h], ld=516
__device__ float g_ymid [(size_t)MTOT * DMODEL + 64]; // irfft out (pre-norm)

// ---------------- weight-prep kernels ----------------
// rfft ortho scale = 1/sqrt(512)
#define ORTHO_SCALE 0.04419417382415922f

__global__ void k_gen_FT() {
    int idx = blockIdx.x * blockDim.x + threadIdx.x;
    if (idx >= FCOLS * DMODEL) return;
    int col = idx / DMODEL;     // output channel 0..513
    int n   = idx - col * DMODEL;
    int k, isIm;
    if (col < 128)      { k = col;             isIm = 0; }
    else if (col < 256) { k = col - 128;       isIm = 1; }
    else if (col < 385) { k = col - 256 + 128; isIm = 0; }  // Re k=128..256
    else                { k = col - 385 + 128; isIm = 1; }  // Im k=128..256
    float a = (float)(k * n) * (1.0f / 256.0f);
    float s, c;
    sincospif(a, &s, &c);
    g_FT[(size_t)col * DMODEL + n] = isIm ? (-s * ORTHO_SCALE) : (c * ORTHO_SCALE);
}

__global__ void k_gen_G() {
    int idx = blockIdx.x * blockDim.x + threadIdx.x;
    if (idx >= DMODEL * FCOLS) return;
    int n = idx / FCOLS;
    int j = idx - n * FCOLS;
    int k = j >> 1;
    float a = (float)(k * n) * (1.0f / 256.0f);
    float s, c;
    sincospif(a, &s, &c);
    float val;
    if ((j & 1) == 0) {          // real component coefficient
        float w = (k == 0 || k == 256) ? 1.0f : 2.0f;
        val = w * c * ORTHO_SCALE;
    } else {                     // imag component (DC/Nyquist imag ignored by irfft)
        val = (k == 0 || k == 256) ? 0.0f : (-2.0f * s * ORTHO_SCALE);
    }
    g_G[(size_t)n * FLD + j] = val;
}

__global__ void k_build_Wt(const float* __restrict__ coeffs) {
    int idx = blockIdx.x * blockDim.x + threadIdx.x;   // over 256*256
    if (idx >= DLOW * DLOW) return;
    int u = idx / DLOW;
    int i = idx - u * DLOW;
    const float* cp = coeffs + ((size_t)u * DLOW + i) * 3;
    g_Wt[(size_t)u * 512 + i]        = cp[1];
    g_Wt[(size_t)u * 512 + 256 + i]  = cp[2];
}

// one block (1 warp) per output channel u
__global__ void k_build_bias(const float* __restrict__ coeffs,
                             const float* __restrict__ tb) {
    int u = blockIdx.x;
    int t = threadIdx.x;          // 32
    float acc = 0.0f;
    const float* cp = coeffs + (size_t)u * DLOW * 3;
#pragma unroll
    for (int i = t; i < DLOW; i += 32) acc += cp[i * 3];
#pragma unroll
    for (int o = 16; o > 0; o >>= 1) acc += __shfl_xor_sync(0xffffffffu, acc, o);
    if (t == 0) g_bias_t[u] = acc + tb[u];
}

// ---------------- 3xTF32 tensor-core NT GEMM ----------------
// C[m,n] = sum_k A[m,k]*B[n,k].  BM=128, BN=64, BK=16, 256 threads.
// 8 warps tiled 4(M) x 2(N), warp tile 32x32, mma.m16n8k8 tf32, 3-pass split.
// Requirements: M % 128 == 0; A rows 16B-aligned (lda % 4 == 0, base 16B-aligned).
// N, K arbitrary (guarded). B loaded with scalar guarded loads (any ldb).

__device__ __forceinline__ uint32_t f2tf(float x) {
    uint32_t r; asm("cvt.rna.tf32.f32 %0, %1;" : "=r"(r) : "f"(x)); return r;
}
__device__ __forceinline__ void splitf(float x, uint32_t& hi, uint32_t& lo) {
    hi = f2tf(x);
    lo = f2tf(x - __uint_as_float(hi));
}

#define MMA_TF32(D, Ar, Br)                                                  \
    asm volatile("mma.sync.aligned.m16n8k8.row.col.f32.tf32.tf32.f32 "       \
                 "{%0,%1,%2,%3}, {%4,%5,%6,%7}, {%8,%9}, {%0,%1,%2,%3};"     \
                 : "+f"(D[0]), "+f"(D[1]), "+f"(D[2]), "+f"(D[3])            \
                 : "r"(Ar[0]), "r"(Ar[1]), "r"(Ar[2]), "r"(Ar[3]),           \
                   "r"(Br[0]), "r"(Br[1]))

__global__ void __launch_bounds__(256, 2)
tgemm_nt(const float* __restrict__ A, int lda,
         const float* __restrict__ B, int ldb,
         float* __restrict__ C, int ldc,
         int N, int K,
         const float* __restrict__ bias, int act)
{
    __shared__ float As[2][16][136];   // [k][m], pad 8 -> conflict-free frags
    __shared__ float Bs[2][16][72];    // [k][n], pad 8

    const int tid = threadIdx.x;
    const int m0 = blockIdx.y * 128;
    const int n0 = blockIdx.x * 64;

    // A loader: thread -> (row am, k-offset ak), 2x float4
    const int am = tid >> 1;
    const int ak = (tid & 1) * 8;
    // B loader: thread -> (col bn, k-offset bk), 4 scalars
    const int bn = tid & 63;
    const int bk = (tid >> 6) * 4;

    const float* Arow = A + (size_t)(m0 + am) * lda;
    const float* Brow = B + (size_t)(n0 + bn) * ldb;
    const bool bval = (n0 + bn) < N;

    const int wid  = tid >> 5;
    const int lane = tid & 31;
    const int wm = (wid & 3) * 32;     // warp row offset in block tile
    const int wn = (wid >> 2) * 32;    // warp col offset
    const int grp = lane >> 2;
    const int qid = lane & 3;

    float acc[2][4][4];
#pragma unroll
    for (int i = 0; i < 2; i++)
#pragma unroll
        for (int j = 0; j < 4; j++)
#pragma unroll
            for (int r = 0; r < 4; r++) acc[i][j][r] = 0.0f;

    const int ntiles = (K + 15) >> 4;
    float a_reg[8];
    float b_reg[4];

    // ---- load tile t into regs ----
#define LOAD_TILE(t)                                                          \
    {                                                                         \
        int k0 = (t) * 16;                                                    \
        if (k0 + 16 <= K) {                                                   \
            float4 v0 = *reinterpret_cast<const float4*>(Arow + k0 + ak);     \
            float4 v1 = *reinterpret_cast<const float4*>(Arow + k0 + ak + 4); \
            a_reg[0] = v0.x; a_reg[1] = v0.y; a_reg[2] = v0.z; a_reg[3] = v0.w;\
            a_reg[4] = v1.x; a_reg[5] = v1.y; a_reg[6] = v1.z; a_reg[7] = v1.w;\
            if (bval) {                                                       \
                b_reg[0] = Brow[k0 + bk + 0]; b_reg[1] = Brow[k0 + bk + 1];   \
                b_reg[2] = Brow[k0 + bk + 2]; b_reg[3] = Brow[k0 + bk + 3];   \
            } else { b_reg[0] = b_reg[1] = b_reg[2] = b_reg[3] = 0.0f; }      \
        } else {                                                              \
            _Pragma("unroll")                                                 \
            for (int c = 0; c < 8; c++) {                                     \
                int kk = k0 + ak + c;                                         \
                a_reg[c] = (kk < K) ? Arow[kk] : 0.0f;                        \
            }                                                                 \
            _Pragma("unroll")                                                 \
            for (int c = 0; c < 4; c++) {                                     \
                int kk = k0 + bk + c;                                         \
                b_reg[c] = (bval && kk < K) ? Brow[kk] : 0.0f;                \
            }                                                                 \
        }                                                                     \
    }

#define STORE_TILE(buf)                                                       \
    {                                                                         \
        _Pragma("unroll")                                                     \
        for (int c = 0; c < 8; c++) As[buf][ak + c][am] = a_reg[c];           \
        _Pragma("unroll")                                                     \
        for (int c = 0; c < 4; c++) Bs[buf][bk + c][bn] = b_reg[c];           \
    }

    LOAD_TILE(0);
    STORE_TILE(0);
    __syncthreads();

    int cur = 0;
    for (int t = 0; t < ntiles; t++) {
        if (t + 1 < ntiles) LOAD_TILE(t + 1);

        // ---- compute on buffer cur ----
#pragma unroll
        for (int ks = 0; ks < 16; ks += 8) {
            uint32_t bh[4][2], bl[4][2];
#pragma unroll
            for (int j = 0; j < 4; j++) {
                float f0 = Bs[cur][ks + qid][wn + j * 8 + grp];
                float f1 = Bs[cur][ks + qid + 4][wn + j * 8 + grp];
                splitf(f0, bh[j][0], bl[j][0]);
                splitf(f1, bh[j][1], bl[j][1]);
            }
#pragma unroll
            for (int i = 0; i < 2; i++) {
                uint32_t ah[4], al[4];
                float f;
                f = As[cur][ks + qid][wm + i * 16 + grp];         splitf(f, ah[0], al[0]);
                f = As[cur][ks + qid][wm + i * 16 + grp + 8];     splitf(f, ah[1], al[1]);
                f = As[cur][ks + qid + 4][wm + i * 16 + grp];     splitf(f, ah[2], al[2]);
                f = As[cur][ks + qid + 4][wm + i * 16 + grp + 8]; splitf(f, ah[3], al[3]);
#pragma unroll
                for (int j = 0; j < 4; j++) {
                    MMA_TF32(acc[i][j], ah, bh[j]);
                    MMA_TF32(acc[i][j], ah, bl[j]);
                    MMA_TF32(acc[i][j], al, bh[j]);
                }
            }
        }

        if (t + 1 < ntiles) {
            STORE_TILE(cur ^ 1);
            __syncthreads();
            cur ^= 1;
        }
    }

    // ---- epilogue ----
#pragma unroll
    for (int i = 0; i < 2; i++) {
#pragma unroll
        for (int j = 0; j < 4; j++) {
            int r0 = m0 + wm + i * 16 + grp;
            int c0 = n0 + wn + j * 8 + qid * 2;
            float v[4] = {acc[i][j][0], acc[i][j][1], acc[i][j][2], acc[i][j][3]};
#pragma unroll
            for (int e = 0; e < 4; e++) {
                int n = c0 + (e & 1);
                if (n < N) {
                    float x = v[e];
                    if (bias) x += bias[n];
                    if (act == 1) x = fmaxf(x, 0.0f) + log1pf(__expf(-fabsf(x)));
                    C[(size_t)(r0 + (e >> 1) * 8) * ldc + n] = x;
                }
            }
        }
    }
}

// ---------------- taylor feature build: [x, x^2] ----------------
__global__ void k_feat() {
    int idx = blockIdx.x * blockDim.x + threadIdx.x;   // MTOT*256
    if (idx >= MTOT * DLOW) return;
    int m = idx / DLOW;
    int i = idx - m * DLOW;
    float v = g_xfcat[(size_t)m * FLD + i];
    g_feat[(size_t)m * 512 + i]       = v;
    g_feat[(size_t)m * 512 + 256 + i] = v * v;
}

// ---------------- depthwise causal conv(4) + silu ----------------
__global__ void k_conv_silu(const float* __restrict__ conv_w,
                            const float* __restrict__ conv_b) {
    int idx = blockIdx.x * blockDim.x + threadIdx.x;   // MTOT*DINNER
    if (idx >= MTOT * DINNER) return;
    int m = idx / DINNER;
    int d = idx - m * DINNER;
    int l = m & (LSEQ - 1);
    const float* w = conv_w + d * 4;
    float acc = conv_b[d];
#pragma unroll
    for (int j = 0; j < 4; j++) {
        int ls = l - 3 + j;
        if (ls >= 0) acc += g_xz[(size_t)(m - 3 + j) * 1032 + d] * w[j];
    }
    float sg = 1.0f / (1.0f + __expf(-acc));
    g_xm[(size_t)m * DINNER + d] = acc * sg;
}

// ---------------- selective scan (thread per (b,d,s), 16-lane reduce) ----------
__global__ void k_scan(const float* __restrict__ A_log,
                       const float* __restrict__ D_param) {
    int g = blockIdx.x * 8 + (threadIdx.x >> 4);   // group index over (b,d)
    int s = threadIdx.x & 15;
    if (g >= NB * DINNER) return;
    int b = g / DINNER;
    int d = g - b * DINNER;

    const float A  = -__expf(A_log[d * DSTATE + s]);
    const float Dv = D_param[d];

    const size_t rowb = (size_t)b * LSEQ;
    const float* dtp = g_dt   + rowb * DINNER + d;
    const float* xp  = g_xm   + rowb * DINNER + d;
    const float* Bp  = g_xdbl + rowb * XDLD + DTRANK + s;
    const float* Cp  = g_xdbl + rowb * XDLD + DTRANK + DSTATE + s;
    const float* zp  = g_xz   + rowb * 1032 + DINNER + d;
    float*       yp  = g_ys   + rowb * DINNER + d;

    float h = 0.0f;
    for (int t = 0; t < LSEQ; t++) {
        float dtv = dtp[(size_t)t * DINNER];
        float xv  = xp [(size_t)t * DINNER];
        float Bv  = Bp [(size_t)t * XDLD];
        float Cv  = Cp [(size_t)t * XDLD];
        h = __expf(dtv * A) * h + (dtv * xv) * Bv;
        float p = h * Cv;
        p += __shfl_xor_sync(0xffffffffu, p, 1);
        p += __shfl_xor_sync(0xffffffffu, p, 2);
        p += __shfl_xor_sync(0xffffffffu, p, 4);
        p += __shfl_xor_sync(0xffffffffu, p, 8);
        if (s == 0) {
            float zv = zp[(size_t)t * 1032];
            float sg = 1.0f / (1.0f + __expf(-zv));
            yp[(size_t)t * DINNER] = (p + xv * Dv) * (zv * sg);
        }
    }
}

// ---------------- RMSNorm * w + residual ----------------
__global__ void k_norm(const float* __restrict__ x,
                       const float* __restrict__ nw,
                       float* __restrict__ out) {
    int m = blockIdx.x;
    const float* yr = g_ymid + (size_t)m * DMODEL;
    float v[4];
    float ss = 0.0f;
#pragma unroll
    for (int i = 0; i < 4; i++) {
        v[i] = yr[threadIdx.x + i * 128];
        ss += v[i] * v[i];
    }
    __shared__ float red[4];
#pragma unroll
    for (int o = 16; o > 0; o >>= 1) ss += __shfl_xor_sync(0xffffffffu, ss, o);
    if ((threadIdx.x & 31) == 0) red[threadIdx.x >> 5] = ss;
    __syncthreads();
    float tot = red[0] + red[1] + red[2] + red[3];
    float rs = rsqrtf(tot * (1.0f / DMODEL) + 1e-5f);
#pragma unroll
    for (int i = 0; i < 4; i++) {
        int n = threadIdx.x + i * 128;
        out[(size_t)m * DMODEL + n] = v[i] * rs * nw[n] + x[(size_t)m * DMODEL + n];
    }
}

// ---------------- launch ----------------
static inline dim3 tg_grid(int N) { return dim3((N + 63) / 64, MTOT / 128); }

extern "C" void kernel_launch(void* const* d_in, const int* in_sizes, int n_in,
                              void* d_out, int out_size) {
    const float* x             = (const float*)d_in[0];
    const float* taylor_coeffs = (const float*)d_in[1];
    const float* taylor_bias   = (const float*)d_in[2];
    const float* in_proj_w     = (const float*)d_in[3];
    const float* conv_w        = (const float*)d_in[4];
    const float* conv_b        = (const float*)d_in[5];
    const float* x_proj_w      = (const float*)d_in[6];
    const float* dt_proj_w     = (const float*)d_in[7];
    const float* dt_proj_b     = (const float*)d_in[8];
    const float* A_log         = (const float*)d_in[9];
    const float* D_param       = (const float*)d_in[10];
    const float* out_proj_w    = (const float*)d_in[11];
    const float* norm_w        = (const float*)d_in[12];
    float* out = (float*)d_out;

    float *p_FT, *p_G, *p_Wt, *p_bias, *p_xfcat, *p_feat, *p_xz, *p_xm,
          *p_xdbl, *p_dt, *p_ys, *p_ycat, *p_ymid;
    cudaGetSymbolAddress((void**)&p_FT,    g_FT);
    cudaGetSymbolAddress((void**)&p_G,     g_G);
    cudaGetSymbolAddress((void**)&p_Wt,    g_Wt);
    cudaGetSymbolAddress((void**)&p_bias,  g_bias_t);
    cudaGetSymbolAddress((void**)&p_xfcat, g_xfcat);
    cudaGetSymbolAddress((void**)&p_feat,  g_feat);
    cudaGetSymbolAddress((void**)&p_xz,    g_xz);
    cudaGetSymbolAddress((void**)&p_xm,    g_xm);
    cudaGetSymbolAddress((void**)&p_xdbl,  g_xdbl);
    cudaGetSymbolAddress((void**)&p_dt,    g_dt);
    cudaGetSymbolAddress((void**)&p_ys,    g_ys);
    cudaGetSymbolAddress((void**)&p_ycat,  g_ycat);
    cudaGetSymbolAddress((void**)&p_ymid,  g_ymid);

    // 1) prep weights
    k_gen_FT<<<(FCOLS * DMODEL + 255) / 256, 256>>>();
    k_gen_G <<<(DMODEL * FCOLS + 255) / 256, 256>>>();
    k_build_Wt<<<(DLOW * DLOW + 255) / 256, 256>>>(taylor_coeffs);
    k_build_bias<<<DLOW, 32>>>(taylor_coeffs, taylor_bias);

    // 2) forward DFT: xfcat = x @ FT^T   (M,514), ldc=516
    tgemm_nt<<<tg_grid(FCOLS), 256>>>(x, DMODEL, p_FT, DMODEL,
                                      p_xfcat, FLD, FCOLS, DMODEL, nullptr, 0);
    // 3) taylor features + GEMM -> ycat[:, 0:256]
    k_feat<<<(MTOT * DLOW + 255) / 256, 256>>>();
    tgemm_nt<<<tg_grid(DLOW), 256>>>(p_feat, 512, p_Wt, 512,
                                     p_ycat, FLD, DLOW, 512, p_bias, 0);
    // 4) mamba in_proj: xz = xh_cat @ in_proj_w^T  (M,1032)
    tgemm_nt<<<tg_grid(1032), 256>>>(p_xfcat + 256, FLD, in_proj_w, DMH,
                                     p_xz, 1032, 1032, DMH, nullptr, 0);
    // 5) conv + silu -> xm
    k_conv_silu<<<(MTOT * DINNER + 255) / 256, 256>>>(conv_w, conv_b);
    // 6) x_proj: xdbl = xm @ x_proj_w^T  (M,49), ldc=52
    tgemm_nt<<<tg_grid(XDBL_C), 256>>>(p_xm, DINNER, x_proj_w, DINNER,
                                       p_xdbl, XDLD, XDBL_C, DINNER, nullptr, 0);
    // 7) dt: softplus(xdbl[:, :17] @ dt_proj_w^T + b)  (M,516)
    tgemm_nt<<<tg_grid(DINNER), 256>>>(p_xdbl, XDLD, dt_proj_w, DTRANK,
                                       p_dt, DINNER, DINNER, DTRANK, dt_proj_b, 1);
    // 8) selective scan (fused +x*D and silu(z) gate) -> ys
    k_scan<<<(NB * DINNER + 7) / 8, 128>>>(A_log, D_param);
    // 9) out_proj -> ycat[:, 256:514]
    tgemm_nt<<<tg_grid(DMH), 256>>>(p_ys, DINNER, out_proj_w, DINNER,
                                    p_ycat + 256, FLD, DMH, DINNER, nullptr, 0);
    // 10) inverse DFT: ymid = ycat @ G^T  (M,512), lda=ldb=516, K=514
    tgemm_nt<<<tg_grid(DMODEL), 256>>>(p_ycat, FLD, p_G, FLD,
                                       p_ymid, DMODEL, DMODEL, FCOLS, nullptr, 0);
    // 11) RMSNorm + residual
    k_norm<<<MTOT, 128>>>(x, norm_w, out);
}